// round 6
// baseline (speedup 1.0000x reference)
#include <cuda_runtime.h>
#include <math.h>

#define N_NODES 100000
#define NUM_E   3200000
#define IN_C    128
#define HID     16

// Scratch (allocation-free rule: __device__ globals).
__device__ __align__(16) float g_deg [N_NODES];
__device__ __align__(16) float g_dinv[N_NODES];
__device__ __align__(16) float g_hs1 [N_NODES * HID];   // (x@W1) * dinv[src]
__device__ __align__(16) float g_agg1[N_NODES * HID];   // scatter target layer 1
__device__ __align__(16) float g_hs2 [N_NODES];         // (relu(...)@W2) * dinv
__device__ __align__(16) float g_agg2[N_NODES];         // scatter target layer 2
__device__ int g_src32[NUM_E];                           // compacted+validated edges
__device__ int g_dst32[NUM_E];
__device__ int g_is64;                                   // edge_index dtype flag

// ---------------------------------------------------------------------------
// K-1: detect whether edge_index buffer is int64 or int32.
// int64 little-endian with values < 2^31 => every odd int32 word is 0.
// int32 real edges => odd words are random IDs in [0,100000); all-zero over
// 8192 samples is impossible.
__global__ void k_detect(const int* __restrict__ ei32) {
    int v = 0;
    for (int i = threadIdx.x; i < 8192; i += 256) v |= ei32[2 * i + 1];
    if (__syncthreads_or(v)) { if (threadIdx.x == 0) g_is64 = 0; }
    else                     { if (threadIdx.x == 0) g_is64 = 1; }
}

// K0: init — agg1=0, agg2=0, deg=1 (self-loop contribution)
__global__ void k_init() {
    int i = blockIdx.x * blockDim.x + threadIdx.x;
    if (i < N_NODES * HID) g_agg1[i] = 0.0f;
    if (i < N_NODES) { g_deg[i] = 1.0f; g_agg2[i] = 0.0f; }
}

// K1: edge compaction (dtype-dispatched, clamped) + degree accumulation
__global__ void k_deg(const void* __restrict__ ei_raw) {
    int t = blockIdx.x * blockDim.x + threadIdx.x;
    if (t >= NUM_E) return;
    int src, dst;
    if (g_is64) {
        const long long* e = (const long long*)ei_raw;
        src = (int)e[t];
        dst = (int)e[NUM_E + t];
    } else {
        const int* e = (const int*)ei_raw;
        src = e[t];
        dst = e[NUM_E + t];
    }
    if ((unsigned)src >= N_NODES) src = 0;   // defensive clamp: no wild atomics
    if ((unsigned)dst >= N_NODES) dst = 0;
    g_src32[t] = src;
    g_dst32[t] = dst;
    atomicAdd(&g_deg[dst], 1.0f);
}

// K2: dinv = rsqrt(deg)   (deg >= 1 always, self-loop)
__global__ void k_dinv() {
    int i = blockIdx.x * blockDim.x + threadIdx.x;
    if (i < N_NODES) g_dinv[i] = rsqrtf(g_deg[i]);
}

// K3: hs1 = (x @ W1) * dinv[node].  8 nodes / block of 128 threads.
__global__ void k_gemm1(const float* __restrict__ x, const float* __restrict__ W1) {
    __shared__ float sW[IN_C * HID];       // 8 KB
    __shared__ float sx[8][IN_C + 1];      // padded: bank-conflict-free
    int tid = threadIdx.x;
    int node0 = blockIdx.x * 8;

    #pragma unroll
    for (int i = tid; i < IN_C * HID; i += 128) sW[i] = W1[i];
    #pragma unroll
    for (int r = 0; r < 8; r++) {
        int node = node0 + r;
        sx[r][tid] = (node < N_NODES) ? x[node * IN_C + tid] : 0.0f;
    }
    __syncthreads();

    int r = tid >> 4;          // 0..7
    int o = tid & 15;          // 0..15
    int node = node0 + r;
    if (node < N_NODES) {
        float s = 0.0f;
        #pragma unroll
        for (int k = 0; k < IN_C; k++) s = fmaf(sx[r][k], sW[k * HID + o], s);
        g_hs1[node * HID + o] = s * g_dinv[node];
    }
}

// K4: scatter layer 1 — 4 threads per edge, 4 scalar atomicAdd each.
__global__ void k_scatter1() {
    long long t = (long long)blockIdx.x * blockDim.x + threadIdx.x;
    if (t >= (long long)NUM_E * 4) return;
    int e = (int)(t >> 2);
    int q = (int)(t & 3);
    int src = g_src32[e];
    int dst = g_dst32[e];
    const float4 v = *reinterpret_cast<const float4*>(&g_hs1[src * HID + q * 4]);
    float* p = &g_agg1[dst * HID + q * 4];
    atomicAdd(p + 0, v.x);
    atomicAdd(p + 1, v.y);
    atomicAdd(p + 2, v.z);
    atomicAdd(p + 3, v.w);
}

// K5: layer-1 epilogue + layer-2 transform:
//   v_c = relu(dinv[i]*(agg1 + hs1_self)_c + b1_c);  hs2[i] = (Σ v_c W2_c) * dinv[i]
__global__ void k_layer2(const float* __restrict__ b1, const float* __restrict__ W2) {
    int i = blockIdx.x * blockDim.x + threadIdx.x;
    if (i >= N_NODES) return;
    float di = g_dinv[i];
    const float4* ag = reinterpret_cast<const float4*>(&g_agg1[i * HID]);
    const float4* hs = reinterpret_cast<const float4*>(&g_hs1[i * HID]);
    float acc = 0.0f;
    #pragma unroll
    for (int q = 0; q < 4; q++) {
        float4 a = ag[q], h = hs[q];
        float v0 = fmaxf(di * (a.x + h.x) + b1[q*4+0], 0.0f);
        float v1 = fmaxf(di * (a.y + h.y) + b1[q*4+1], 0.0f);
        float v2 = fmaxf(di * (a.z + h.z) + b1[q*4+2], 0.0f);
        float v3 = fmaxf(di * (a.w + h.w) + b1[q*4+3], 0.0f);
        acc += v0 * W2[q*4+0] + v1 * W2[q*4+1] + v2 * W2[q*4+2] + v3 * W2[q*4+3];
    }
    g_hs2[i] = acc * di;
}

// K6: scatter layer 2 — scalar reductions
__global__ void k_scatter2() {
    int t = blockIdx.x * blockDim.x + threadIdx.x;
    if (t >= NUM_E) return;
    int src = g_src32[t];
    int dst = g_dst32[t];
    atomicAdd(&g_agg2[dst], g_hs2[src]);
}

// K7: final — sigmoid(dinv[i]*(agg2 + hs2_self) + b2)
__global__ void k_final(const float* __restrict__ b2, float* __restrict__ out) {
    int i = blockIdx.x * blockDim.x + threadIdx.x;
    if (i >= N_NODES) return;
    float z = g_dinv[i] * (g_agg2[i] + g_hs2[i]) + b2[0];
    out[i] = 1.0f / (1.0f + expf(-z));
}

// ---------------------------------------------------------------------------
extern "C" void kernel_launch(void* const* d_in, const int* in_sizes, int n_in,
                              void* d_out, int out_size) {
    const float* x  = (const float*)d_in[0];
    const void*  ei = d_in[1];                 // edge_index: int64 OR int32 [2,E]
    const float* W1 = (const float*)d_in[2];
    const float* b1 = (const float*)d_in[3];
    const float* W2 = (const float*)d_in[4];
    const float* b2 = (const float*)d_in[5];
    float* out = (float*)d_out;

    (void)in_sizes; (void)n_in; (void)out_size;

    const int T = 256;
    k_detect  <<<1, 256>>>((const int*)ei);
    k_init    <<<(N_NODES * HID + T - 1) / T, T>>>();
    k_deg     <<<(NUM_E + T - 1) / T, T>>>(ei);
    k_dinv    <<<(N_NODES + T - 1) / T, T>>>();
    k_gemm1   <<<(N_NODES + 7) / 8, 128>>>(x, W1);
    {
        long long total = (long long)NUM_E * 4;
        k_scatter1<<<(unsigned)((total + T - 1) / T), T>>>();
    }
    k_layer2  <<<(N_NODES + T - 1) / T, T>>>(b1, W2);
    k_scatter2<<<(NUM_E + T - 1) / T, T>>>();
    k_final   <<<(N_NODES + T - 1) / T, T>>>(b2, out);
}

// round 16
// speedup vs baseline: 1.3622x; 1.3622x over previous
#include <cuda_runtime.h>
#include <math.h>

#define N_NODES 100000
#define NUM_E   3200000
#define IN_C    128
#define HID     16

// Scratch (allocation-free rule: __device__ globals).
__device__ __align__(16) float g_deg [N_NODES];
__device__ __align__(16) float g_dinv[N_NODES];
__device__ __align__(16) float g_hs1 [N_NODES * HID];   // (x@W1) * dinv[src]
__device__ __align__(16) float g_agg1[N_NODES * HID];   // scatter target layer 1
__device__ __align__(16) float g_hs2 [N_NODES];         // (relu(...)@W2) * dinv
__device__ __align__(16) float g_agg2[N_NODES];         // scatter target layer 2
__device__ int g_src32[NUM_E];                           // compacted edges (int64 path only)
__device__ int g_dst32[NUM_E];
__device__ int g_is64;                                   // edge_index dtype flag

// ---------------------------------------------------------------------------
// K-1: detect int64 vs int32 edge_index. int64 LE with values < 2^31 => every
// odd int32 word is 0; int32 real edges => essentially impossible all-zero.
__global__ void k_detect(const int* __restrict__ ei32) {
    int v = 0;
    for (int i = threadIdx.x; i < 8192; i += 256) v |= ei32[2 * i + 1];
    if (__syncthreads_or(v)) { if (threadIdx.x == 0) g_is64 = 0; }
    else                     { if (threadIdx.x == 0) g_is64 = 1; }
}

// K0: init — agg1=0, agg2=0, deg=1 (self-loop contribution)
__global__ void k_init() {
    int i = blockIdx.x * blockDim.x + threadIdx.x;
    if (i < N_NODES * HID) g_agg1[i] = 0.0f;
    if (i < N_NODES) { g_deg[i] = 1.0f; g_agg2[i] = 0.0f; }
}

// Clamped index helper — wild atomics are how we got err717; never again.
__device__ __forceinline__ int clampN(int v) {
    return ((unsigned)v < N_NODES) ? v : 0;
}

// K1: degree accumulation (+ compaction only on the int64 path)
__global__ void k_deg(const void* __restrict__ ei_raw) {
    int t = blockIdx.x * blockDim.x + threadIdx.x;
    if (t >= NUM_E) return;
    int dst;
    if (g_is64) {
        const long long* e = (const long long*)ei_raw;
        int src = clampN((int)e[t]);
        dst     = clampN((int)e[NUM_E + t]);
        g_src32[t] = src;
        g_dst32[t] = dst;
    } else {
        const int* e = (const int*)ei_raw;
        dst = clampN(e[NUM_E + t]);
    }
    atomicAdd(&g_deg[dst], 1.0f);
}

// K2: dinv = rsqrt(deg)   (deg >= 1 always, self-loop)
__global__ void k_dinv() {
    int i = blockIdx.x * blockDim.x + threadIdx.x;
    if (i < N_NODES) g_dinv[i] = rsqrtf(g_deg[i]);
}

// K3: hs1 = (x @ W1) * dinv[node].  8 nodes / block of 128 threads.
__global__ void k_gemm1(const float* __restrict__ x, const float* __restrict__ W1) {
    __shared__ float sW[IN_C * HID];       // 8 KB
    __shared__ float sx[8][IN_C + 1];      // padded: bank-conflict-free
    int tid = threadIdx.x;
    int node0 = blockIdx.x * 8;

    #pragma unroll
    for (int i = tid; i < IN_C * HID; i += 128) sW[i] = W1[i];
    #pragma unroll
    for (int r = 0; r < 8; r++) {
        int node = node0 + r;
        sx[r][tid] = (node < N_NODES) ? x[node * IN_C + tid] : 0.0f;
    }
    __syncthreads();

    int r = tid >> 4;          // 0..7
    int o = tid & 15;          // 0..15
    int node = node0 + r;
    if (node < N_NODES) {
        float s = 0.0f;
        #pragma unroll
        for (int k = 0; k < IN_C; k++) s = fmaf(sx[r][k], sW[k * HID + o], s);
        g_hs1[node * HID + o] = s * g_dinv[node];
    }
}

// K4: scatter layer 1 — 4 threads/edge, ONE red.global.add.v4.f32 each
// (12.8M vector REDs vs 51.2M scalar atomics). Addresses clamped + 16B aligned.
__global__ void k_scatter1(const int* __restrict__ ei32) {
    long long t = (long long)blockIdx.x * blockDim.x + threadIdx.x;
    if (t >= (long long)NUM_E * 4) return;
    int e = (int)(t >> 2);
    int q = (int)(t & 3);
    int src, dst;
    if (g_is64) {
        src = g_src32[e];
        dst = g_dst32[e];
    } else {
        src = clampN(ei32[e]);
        dst = clampN(ei32[NUM_E + e]);
    }
    const float4 v = *reinterpret_cast<const float4*>(&g_hs1[src * HID + q * 4]);
    size_t gp = __cvta_generic_to_global(&g_agg1[dst * HID + q * 4]);
    asm volatile("red.global.add.v4.f32 [%0], {%1, %2, %3, %4};"
                 :: "l"(gp), "f"(v.x), "f"(v.y), "f"(v.z), "f"(v.w) : "memory");
}

// K5: layer-1 epilogue + layer-2 transform:
//   v_c = relu(dinv[i]*(agg1 + hs1_self)_c + b1_c);  hs2[i] = (Σ v_c W2_c) * dinv[i]
__global__ void k_layer2(const float* __restrict__ b1, const float* __restrict__ W2) {
    int i = blockIdx.x * blockDim.x + threadIdx.x;
    if (i >= N_NODES) return;
    float di = g_dinv[i];
    const float4* ag = reinterpret_cast<const float4*>(&g_agg1[i * HID]);
    const float4* hs = reinterpret_cast<const float4*>(&g_hs1[i * HID]);
    float acc = 0.0f;
    #pragma unroll
    for (int q = 0; q < 4; q++) {
        float4 a = ag[q], h = hs[q];
        float v0 = fmaxf(di * (a.x + h.x) + b1[q*4+0], 0.0f);
        float v1 = fmaxf(di * (a.y + h.y) + b1[q*4+1], 0.0f);
        float v2 = fmaxf(di * (a.z + h.z) + b1[q*4+2], 0.0f);
        float v3 = fmaxf(di * (a.w + h.w) + b1[q*4+3], 0.0f);
        acc += v0 * W2[q*4+0] + v1 * W2[q*4+1] + v2 * W2[q*4+2] + v3 * W2[q*4+3];
    }
    g_hs2[i] = acc * di;
}

// K6: scatter layer 2 — 3.2M scalar reductions (cheap)
__global__ void k_scatter2(const int* __restrict__ ei32) {
    int t = blockIdx.x * blockDim.x + threadIdx.x;
    if (t >= NUM_E) return;
    int src, dst;
    if (g_is64) {
        src = g_src32[t];
        dst = g_dst32[t];
    } else {
        src = clampN(ei32[t]);
        dst = clampN(ei32[NUM_E + t]);
    }
    atomicAdd(&g_agg2[dst], g_hs2[src]);
}

// K7: final — sigmoid(dinv[i]*(agg2 + hs2_self) + b2)
__global__ void k_final(const float* __restrict__ b2, float* __restrict__ out) {
    int i = blockIdx.x * blockDim.x + threadIdx.x;
    if (i >= N_NODES) return;
    float z = g_dinv[i] * (g_agg2[i] + g_hs2[i]) + b2[0];
    out[i] = 1.0f / (1.0f + expf(-z));
}

// ---------------------------------------------------------------------------
extern "C" void kernel_launch(void* const* d_in, const int* in_sizes, int n_in,
                              void* d_out, int out_size) {
    const float* x  = (const float*)d_in[0];
    const void*  ei = d_in[1];                 // edge_index: int64 OR int32 [2,E]
    const float* W1 = (const float*)d_in[2];
    const float* b1 = (const float*)d_in[3];
    const float* W2 = (const float*)d_in[4];
    const float* b2 = (const float*)d_in[5];
    float* out = (float*)d_out;

    (void)in_sizes; (void)n_in; (void)out_size;

    const int T = 256;
    k_detect  <<<1, 256>>>((const int*)ei);
    k_init    <<<(N_NODES * HID + T - 1) / T, T>>>();
    k_deg     <<<(NUM_E + T - 1) / T, T>>>(ei);
    k_dinv    <<<(N_NODES + T - 1) / T, T>>>();
    k_gemm1   <<<(N_NODES + 7) / 8, 128>>>(x, W1);
    {
        long long total = (long long)NUM_E * 4;
        k_scatter1<<<(unsigned)((total + T - 1) / T), T>>>((const int*)ei);
    }
    k_layer2  <<<(N_NODES + T - 1) / T, T>>>(b1, W2);
    k_scatter2<<<(NUM_E + T - 1) / T, T>>>((const int*)ei);
    k_final   <<<(N_NODES + T - 1) / T, T>>>(b2, out);
}